// round 15
// baseline (speedup 1.0000x reference)
#include <cuda_runtime.h>
#include <cuda_fp16.h>
#include <cuda_bf16.h>
#include <cstdint>

#define B_  4
#define N_  4096
#define D_  256
#define HH  8
#define PP  9
#define DH  32
#define M_  (B_*N_)   // 16384
#define NOFF 144
#define NATT 72
#define NOA  216

// ---------------- device scratch (static) ----------------------------------
__device__ uint2  g_bfrag0[16 * 32 * 2 * 32];   // W_off|W_attn bf16 hi/lo (zero-padded)
__device__ uint2  g_bfrag1[16 * 32 * 2 * 32];   // W_v  fp16 (term0 = 64*W)
__device__ uint2  g_bfrag2[16 * 32 * 2 * 32];   // W_o  fp16 (term0 = 64*W)
__device__ float  g_boa[NOA];
__device__ float  g_offattn[(size_t)M_ * NOA];
__device__ __half g_vimg[(size_t)M_ * D_];      // [(b*8+h)][n=y*64+x][c]
__device__ __half g_headout[(size_t)M_ * D_];

// ---------------- helpers ----------------------------------------------------
__device__ __forceinline__ uint32_t bf2bits(float a, float b) {
    __nv_bfloat162 h = __floats2bfloat162_rn(a, b);
    return *reinterpret_cast<uint32_t*>(&h);
}
__device__ __forceinline__ uint32_t h2bits(float a, float b) {
    __half2 h = __floats2half2_rn(a, b);
    return *reinterpret_cast<uint32_t*>(&h);
}
__device__ __forceinline__ uint32_t smem_u32(const void* p) {
    uint32_t a;
    asm("{ .reg .u64 t; cvta.to.shared.u64 t, %1; cvt.u32.u64 %0, t; }"
        : "=r"(a) : "l"(p));
    return a;
}
__device__ __forceinline__ void mma_bf16(float* c,
        uint32_t a0, uint32_t a1, uint32_t a2, uint32_t a3,
        uint32_t b0, uint32_t b1) {
    asm("mma.sync.aligned.m16n8k16.row.col.f32.bf16.bf16.f32 "
        "{%0,%1,%2,%3}, {%4,%5,%6,%7}, {%8,%9}, {%0,%1,%2,%3};"
        : "+f"(c[0]), "+f"(c[1]), "+f"(c[2]), "+f"(c[3])
        : "r"(a0), "r"(a1), "r"(a2), "r"(a3), "r"(b0), "r"(b1));
}
__device__ __forceinline__ void mma_f16(float* c,
        uint32_t a0, uint32_t a1, uint32_t a2, uint32_t a3,
        uint32_t b0, uint32_t b1) {
    asm("mma.sync.aligned.m16n8k16.row.col.f32.f16.f16.f32 "
        "{%0,%1,%2,%3}, {%4,%5,%6,%7}, {%8,%9}, {%0,%1,%2,%3};"
        : "+f"(c[0]), "+f"(c[1]), "+f"(c[2]), "+f"(c[3])
        : "r"(a0), "r"(a1), "r"(a2), "r"(a3), "r"(b0), "r"(b1));
}
__device__ __forceinline__ void ldsm4(uint32_t addr,
        uint32_t& r0, uint32_t& r1, uint32_t& r2, uint32_t& r3) {
    asm volatile("ldmatrix.sync.aligned.m8n8.x4.shared.b16 {%0,%1,%2,%3}, [%4];"
                 : "=r"(r0), "=r"(r1), "=r"(r2), "=r"(r3) : "r"(addr));
}

// ---------------- pack: B -> fragment order -----------------------------------
__global__ void __launch_bounds__(256) pack_kernel(
        const float* __restrict__ Woff, const float* __restrict__ boff,
        const float* __restrict__ Watt, const float* __restrict__ batt,
        const float* __restrict__ Wv,   const float* __restrict__ Wo) {
    int idx = blockIdx.x * 256 + threadIdx.x;
    int mat = blockIdx.y;
    int lane = idx & 31;
    int term = (idx >> 5) & 1;
    int j    = (idx >> 6) & 31;
    int kk   = idx >> 11;
    int gid = lane >> 2, tig = lane & 3;
    int n = j * 8 + gid;
    int k0 = kk * 16 + tig * 2;

    float v[4];
#pragma unroll
    for (int q = 0; q < 4; q++) {
        int k = k0 + (q & 1) + (q >> 1) * 8;
        float w = 0.f;
        if (mat == 0) {
            if (n < NOFF)      w = Woff[k * NOFF + n];
            else if (n < NOA)  w = Watt[k * NATT + (n - NOFF)];
        } else if (mat == 1) {
            w = Wv[k * 256 + n];
        } else {
            w = Wo[k * 256 + n];
        }
        v[q] = w;
    }
    uint2 r;
    if (mat == 0) {
        if (term == 1) {
#pragma unroll
            for (int q = 0; q < 4; q++) {
                float hi = __bfloat162float(__float2bfloat16(v[q]));
                v[q] = v[q] - hi;
            }
        }
        r = make_uint2(bf2bits(v[0], v[1]), bf2bits(v[2], v[3]));
    } else {
#pragma unroll
        for (int q = 0; q < 4; q++) {
            float w64 = v[q] * 64.0f;
            if (term == 0) {
                v[q] = w64;
            } else {
                float hi = __half2float(__float2half_rn(w64));
                v[q] = w64 - hi;
            }
        }
        r = make_uint2(h2bits(v[0], v[1]), h2bits(v[2], v[3]));
    }
    if (mat == 0)      g_bfrag0[idx] = r;
    else if (mat == 1) g_bfrag1[idx] = r;
    else               g_bfrag2[idx] = r;

    if (mat == 0 && idx < NOA)
        g_boa[idx] = (idx < NOFF) ? boff[idx] : batt[idx - NOFF];
}

// ---------------- mma.sync GEMM: BM=128, BN=256, 512 thr, 1 CTA/SM -----------
// TERMS 3: A bf16 hi/lo, B bf16 hi/lo (3-term fp32 emu, offattn).
// TERMS 1: A fp16, B fp16 of 64*W, single MMA per step (vimg, W_o).
// AMODE 0: fp32 rows (lda); AMODE 1: sum of 3 temporal fp32 rows; AMODE 2: fp16 rows
// CMODE 0: fp32 row-major [ldc]; CMODE 1: fp16 vimg scatter
#define APITCH 528           // 256 elems * 2B + 16B pad
#define PLANE  (128 * APITCH)
template<int TERMS, int AMODE, int CMODE, int NCOUT>
__global__ void __launch_bounds__(512, 1) gemm_mma(
        const void* __restrict__ Av, int lda,
        const uint2* __restrict__ Bfrag,
        const float* __restrict__ bias, float bscale,
        float* __restrict__ C, int ldc)
{
    extern __shared__ char smem[];
    char* HI = smem;
    const int tid = threadIdx.x;
    const int wid = tid >> 5, lane = tid & 31;
    const int warp_m = wid & 1, warp_n = wid >> 1;   // 2 x 8 warp grid
    const int mtile = blockIdx.x * 128;
    const int nbase = warp_n * 32;
    const int gid = lane >> 2, tig = lane & 3;
    const bool active = (TERMS != 3) || (nbase < NOA);

    // ---- stage A tile: 128 rows x 256, 4 threads per row ----
    {
        const int row = tid >> 2;
        const int kcolq = (tid & 3) * 64;
        const int sw = (row & 7) << 5;
        char* hp = HI + row * APITCH;
        if (AMODE == 2) {
            const __half* Ap = (const __half*)Av + (size_t)(mtile + row) * lda + kcolq;
#pragma unroll
            for (int c = 0; c < 4; c++) {
                uint4 u0 = *(const uint4*)(Ap + c * 16);
                uint4 u1 = *(const uint4*)(Ap + c * 16 + 8);
                const int XS = ((tid & 3) * 128 + c * 32) ^ sw;
                *(uint4*)(hp + XS)      = u0;
                *(uint4*)(hp + XS + 16) = u1;
            }
        } else {
            const float* Ap = (const float*)Av + (size_t)(mtile + row) * lda + kcolq;
#pragma unroll
            for (int c = 0; c < 4; c++) {
                float v[16];
#pragma unroll
                for (int q = 0; q < 4; q++) {
                    float4 t0 = *(const float4*)(Ap + c * 16 + q * 4);
                    if (AMODE == 1) {
                        float4 t1 = *(const float4*)(Ap + c * 16 + q * 4 + 256);
                        float4 t2 = *(const float4*)(Ap + c * 16 + q * 4 + 512);
                        t0.x += t1.x + t2.x; t0.y += t1.y + t2.y;
                        t0.z += t1.z + t2.z; t0.w += t1.w + t2.w;
                    }
                    v[q * 4 + 0] = t0.x; v[q * 4 + 1] = t0.y;
                    v[q * 4 + 2] = t0.z; v[q * 4 + 3] = t0.w;
                }
                const int XS = ((tid & 3) * 128 + c * 32) ^ sw;
                if (TERMS == 1) {
                    uint32_t hp8[8];
#pragma unroll
                    for (int e = 0; e < 8; e++)
                        hp8[e] = h2bits(v[2 * e], v[2 * e + 1]);
                    *(uint4*)(hp + XS)      = make_uint4(hp8[0], hp8[1], hp8[2], hp8[3]);
                    *(uint4*)(hp + XS + 16) = make_uint4(hp8[4], hp8[5], hp8[6], hp8[7]);
                } else {
                    uint32_t hp8[8], lp8[8];
#pragma unroll
                    for (int e = 0; e < 8; e++) {
                        float v0 = v[2 * e], v1 = v[2 * e + 1];
                        float h0 = __bfloat162float(__float2bfloat16(v0));
                        float h1 = __bfloat162float(__float2bfloat16(v1));
                        hp8[e] = bf2bits(v0, v1);
                        lp8[e] = bf2bits(v0 - h0, v1 - h1);
                    }
                    *(uint4*)(hp + XS)              = make_uint4(hp8[0], hp8[1], hp8[2], hp8[3]);
                    *(uint4*)(hp + XS + 16)         = make_uint4(hp8[4], hp8[5], hp8[6], hp8[7]);
                    *(uint4*)(hp + PLANE + XS)      = make_uint4(lp8[0], lp8[1], lp8[2], lp8[3]);
                    *(uint4*)(hp + PLANE + XS + 16) = make_uint4(lp8[4], lp8[5], lp8[6], lp8[7]);
                }
            }
        }
    }

    // ---- B prefetch ----
    const int jg = warp_n * 4;
    const uint2* Bp = Bfrag + (size_t)jg * 64 + lane;
    uint2 bbuf[2][4][2];
    if (active) {
#pragma unroll
        for (int j = 0; j < 4; j++) {
            bbuf[0][j][0] = __ldg(Bp + j * 64);
            bbuf[1][j][0] = __ldg(Bp + 2048 + j * 64);
            if (TERMS == 3) {
                bbuf[0][j][1] = __ldg(Bp + j * 64 + 32);
                bbuf[1][j][1] = __ldg(Bp + 2048 + j * 64 + 32);
            }
        }
    }

    float acc[4][4][4];
#pragma unroll
    for (int mt = 0; mt < 4; mt++)
#pragma unroll
        for (int j = 0; j < 4; j++)
#pragma unroll
            for (int q = 0; q < 4; q++) acc[mt][j][q] = 0.f;

    __syncthreads();

    const int lrow = warp_m * 64 + (lane & 15);
    const uint32_t lanec = (lane >> 4) << 4;
    const uint32_t swr = (lrow & 7) << 5;
    const uint32_t hibase = smem_u32(HI + lrow * APITCH) + lanec;

    if (TERMS == 1) {
        uint32_t af[2][4];
        ldsm4(hibase + (0u ^ swr), af[0][0], af[0][1], af[0][2], af[0][3]);
        for (int kk = 0; kk < 16; kk++) {
            const int buf = kk & 1;
#pragma unroll
            for (int mt = 0; mt < 4; mt++) {
                const int cur = mt & 1;
                if (!(kk == 15 && mt == 3)) {
                    const int nmt = (mt + 1) & 3;
                    const int nkk = (mt == 3) ? kk + 1 : kk;
                    const uint32_t nkoff = ((uint32_t)(nkk * 32)) ^ swr;
                    ldsm4(hibase + nmt * (16 * APITCH) + nkoff,
                          af[cur ^ 1][0], af[cur ^ 1][1], af[cur ^ 1][2], af[cur ^ 1][3]);
                }
#pragma unroll
                for (int j = 0; j < 4; j++)
                    mma_f16(acc[mt][j], af[cur][0], af[cur][1], af[cur][2], af[cur][3],
                            bbuf[buf][j][0].x, bbuf[buf][j][0].y);
            }
            if (kk < 14) {
                const uint2* Bn = Bp + (size_t)(kk + 2) * 2048;
#pragma unroll
                for (int j = 0; j < 4; j++)
                    bbuf[buf][j][0] = __ldg(Bn + j * 64);
            }
        }
    } else if (active) {
        for (int kk = 0; kk < 16; kk++) {
            const uint32_t koff = ((uint32_t)(kk * 32)) ^ swr;
            const int buf = kk & 1;
#pragma unroll
            for (int mt = 0; mt < 4; mt++) {
                uint32_t ah0, ah1, ah2, ah3, al0, al1, al2, al3;
                uint32_t ad = hibase + mt * (16 * APITCH) + koff;
                ldsm4(ad, ah0, ah1, ah2, ah3);
                ldsm4(ad + PLANE, al0, al1, al2, al3);
#pragma unroll
                for (int j = 0; j < 4; j++)
                    mma_bf16(acc[mt][j], ah0, ah1, ah2, ah3,
                             bbuf[buf][j][0].x, bbuf[buf][j][0].y);
#pragma unroll
                for (int j = 0; j < 4; j++)
                    mma_bf16(acc[mt][j], al0, al1, al2, al3,
                             bbuf[buf][j][0].x, bbuf[buf][j][0].y);
#pragma unroll
                for (int j = 0; j < 4; j++)
                    mma_bf16(acc[mt][j], ah0, ah1, ah2, ah3,
                             bbuf[buf][j][1].x, bbuf[buf][j][1].y);
            }
            if (kk < 14) {
                const uint2* Bn = Bp + (size_t)(kk + 2) * 2048;
#pragma unroll
                for (int j = 0; j < 4; j++)
#pragma unroll
                    for (int t = 0; t < 2; t++)
                        bbuf[buf][j][t] = __ldg(Bn + j * 64 + t * 32);
            }
        }
    }

    // ---- epilogue ----
    const float cscale = (TERMS == 1) ? (1.0f / 64.0f) : 1.0f;
#pragma unroll
    for (int mt = 0; mt < 4; mt++) {
        int row0 = mtile + warp_m * 64 + mt * 16 + gid;
#pragma unroll
        for (int j = 0; j < 4; j++) {
            int col = nbase + j * 8 + tig * 2;
            if (col >= NCOUT) continue;
            float b0 = fmaf(bscale, bias[col],     acc[mt][j][0] * cscale);
            float b1 = fmaf(bscale, bias[col + 1], acc[mt][j][1] * cscale);
            float b2 = fmaf(bscale, bias[col],     acc[mt][j][2] * cscale);
            float b3 = fmaf(bscale, bias[col + 1], acc[mt][j][3] * cscale);
            if (CMODE == 0) {
                *(float2*)&C[(size_t)row0 * ldc + col] = make_float2(b0, b1);
                *(float2*)&C[(size_t)(row0 + 8) * ldc + col] = make_float2(b2, b3);
            } else {
                int h = col >> 5, cc = col & 31;
                int bb0 = row0 >> 12, nn0 = row0 & 4095;
                int gm1 = row0 + 8;
                int bb1 = gm1 >> 12, nn1 = gm1 & 4095;
                *(__half2*)&g_vimg[(((size_t)(bb0 * 8 + h) * 4096 + nn0) << 5) + cc] =
                    __floats2half2_rn(b0, b1);
                *(__half2*)&g_vimg[(((size_t)(bb1 * 8 + h) * 4096 + nn1) << 5) + cc] =
                    __floats2half2_rn(b2, b3);
            }
        }
    }
}

// ---------------- sampling: 4 bn/block, half2 FMA inner loop, fp16 out --------
__global__ void __launch_bounds__(256) sample_kernel() {
    __shared__ int4  s_idx[4][HH * PP];
    __shared__ uint4 s_wgt[4][HH * PP];    // 4 half2-splatted corner weights

    const int bn0 = blockIdx.x * 4;
    const int t = threadIdx.x;

#pragma unroll
    for (int e = t; e < 4 * HH * PP; e += 256) {
        const int sub = e / (HH * PP);
        const int hp = e - sub * (HH * PP);
        const int h = hp / PP;
        const int p = hp - h * PP;
        const int bn = bn0 + sub;
        const int n = bn & 4095;
        const float* oa = g_offattn + (size_t)bn * NOA;

        float mx = -1e30f;
#pragma unroll
        for (int q = 0; q < PP; q++) mx = fmaxf(mx, oa[NOFF + h * PP + q]);
        float s = 0.f;
#pragma unroll
        for (int q = 0; q < PP; q++) s += __expf(oa[NOFF + h * PP + q] - mx);
        const float wa = __expf(oa[NOFF + h * PP + p] - mx) / s;

        const float ref_xn = (float)(n & 63) * (2.0f / 63.0f) - 1.0f;
        const float ref_yn = (float)(n >> 6) * (2.0f / 63.0f) - 1.0f;
        float ox = oa[h * 18 + p * 2 + 0];
        float oy = oa[h * 18 + p * 2 + 1];
        float gx = (ref_xn + ox + 1.0f) * 0.5f * 63.0f;
        float gy = (ref_yn + oy + 1.0f) * 0.5f * 63.0f;
        float x0f = floorf(gx), y0f = floorf(gy);
        int x0 = (int)x0f, y0 = (int)y0f;
        float wx1 = gx - x0f, wy1 = gy - y0f;
        float wx0 = 1.f - wx1, wy0 = 1.f - wy1;

        float vx0 = (x0 >= 0 && x0 < 64) ? 1.f : 0.f;
        float vx1 = (x0 >= -1 && x0 < 63) ? 1.f : 0.f;
        float vy0 = (y0 >= 0 && y0 < 64) ? 1.f : 0.f;
        float vy1 = (y0 >= -1 && y0 < 63) ? 1.f : 0.f;

        int cx0 = min(max(x0, 0), 63);
        int cx1 = min(max(x0 + 1, 0), 63);
        int cy0 = min(max(y0, 0), 63) * 64;
        int cy1 = min(max(y0 + 1, 0), 63) * 64;

        s_idx[sub][hp] = make_int4(cy0 + cx0, cy0 + cx1, cy1 + cx0, cy1 + cx1);
        __half2 w00 = __float2half2_rn(wa * wx0 * wy0 * vx0 * vy0);
        __half2 w10 = __float2half2_rn(wa * wx1 * wy0 * vx1 * vy0);
        __half2 w01 = __float2half2_rn(wa * wx0 * wy1 * vx0 * vy1);
        __half2 w11 = __float2half2_rn(wa * wx1 * wy1 * vx1 * vy1);
        s_wgt[sub][hp] = make_uint4(*reinterpret_cast<uint32_t*>(&w00),
                                    *reinterpret_cast<uint32_t*>(&w10),
                                    *reinterpret_cast<uint32_t*>(&w01),
                                    *reinterpret_cast<uint32_t*>(&w11));
    }
    __syncthreads();

    const int sub = t >> 6;
    const int r = t & 63;
    const int h = r >> 3;
    const int c4 = r & 7;
    const int bn = bn0 + sub;
    const int b = bn >> 12;

    const uint2* img8 = (const uint2*)g_vimg
                      + (((size_t)(b * 8 + h) * 4096) << 3) + c4;

    float a0 = 0.f, a1 = 0.f, a2 = 0.f, a3 = 0.f;
#pragma unroll
    for (int p = 0; p < PP; p++) {
        int4  id = s_idx[sub][h * PP + p];
        uint4 wq = s_wgt[sub][h * PP + p];
        __half2 s0 = __float2half2_rn(0.f);
        __half2 s1 = __float2half2_rn(0.f);
#pragma unroll
        for (int cr = 0; cr < 4; cr++) {
            int idx = (cr == 0) ? id.x : (cr == 1) ? id.y : (cr == 2) ? id.z : id.w;
            uint32_t wb = (cr == 0) ? wq.x : (cr == 1) ? wq.y : (cr == 2) ? wq.z : wq.w;
            __half2 wh = *reinterpret_cast<__half2*>(&wb);
            uint2 v = __ldg(img8 + ((size_t)idx << 3));
            s0 = __hfma2(wh, *reinterpret_cast<__half2*>(&v.x), s0);
            s1 = __hfma2(wh, *reinterpret_cast<__half2*>(&v.y), s1);
        }
        float2 f0 = __half22float2(s0);
        float2 f1 = __half22float2(s1);
        a0 += f0.x; a1 += f0.y; a2 += f1.x; a3 += f1.y;
    }
    uint2 outv = make_uint2(h2bits(a0, a1), h2bits(a2, a3));
    *(uint2*)&g_headout[(size_t)bn * D_ + h * DH + c4 * 4] = outv;
}

// ---------------- launch --------------------------------------------------------
extern "C" void kernel_launch(void* const* d_in, const int* in_sizes, int n_in,
                              void* d_out, int out_size) {
    const float* x      = (const float*)d_in[0];
    const float* W_off  = (const float*)d_in[1];
    const float* b_off  = (const float*)d_in[2];
    const float* W_attn = (const float*)d_in[3];
    const float* b_attn = (const float*)d_in[4];
    const float* W_v    = (const float*)d_in[5];
    const float* b_v    = (const float*)d_in[6];
    const float* W_o    = (const float*)d_in[7];
    const float* b_o    = (const float*)d_in[8];
    float* out = (float*)d_out;

    uint2 *p_bf0, *p_bf1, *p_bf2;
    float *p_boa, *p_offattn;
    __half* p_headout;
    cudaGetSymbolAddress((void**)&p_bf0,     g_bfrag0);
    cudaGetSymbolAddress((void**)&p_bf1,     g_bfrag1);
    cudaGetSymbolAddress((void**)&p_bf2,     g_bfrag2);
    cudaGetSymbolAddress((void**)&p_boa,     g_boa);
    cudaGetSymbolAddress((void**)&p_offattn, g_offattn);
    cudaGetSymbolAddress((void**)&p_headout, g_headout);

    cudaFuncSetAttribute(gemm_mma<3, 0, 0, NOA>,
                         cudaFuncAttributeMaxDynamicSharedMemorySize, 2 * PLANE);
    cudaFuncSetAttribute(gemm_mma<1, 1, 1, 256>,
                         cudaFuncAttributeMaxDynamicSharedMemorySize, PLANE);
    cudaFuncSetAttribute(gemm_mma<1, 2, 0, 256>,
                         cudaFuncAttributeMaxDynamicSharedMemorySize, PLANE);

    // 1. pack weights into fragment order
    pack_kernel<<<dim3(128, 3), 256>>>(W_off, b_off, W_attn, b_attn, W_v, W_o);

    // 2. value images: (sum_t x) @ W_v + 3*b_v -> fp16 vimg (1-term fp16)
    gemm_mma<1, 1, 1, 256><<<128, 512, PLANE>>>(
        x, 768, p_bf1, b_v, 3.0f, nullptr, 0);

    // 3. offsets + attn logits: query @ [W_off|W_attn] (3-term bf16, pad warps skipped)
    gemm_mma<3, 0, 0, NOA><<<128, 512, 2 * PLANE>>>(
        x + 256, 768, p_bf0, p_boa, 1.0f, p_offattn, NOA);

    // 4. softmax + bilinear sampling + attention reduce -> fp16 headout
    sample_kernel<<<M_ / 4, 256>>>();

    // 5. output projection: headout(fp16) @ W_o + b_o (1-term fp16)
    gemm_mma<1, 2, 0, 256><<<128, 512, PLANE>>>(
        p_headout, 256, p_bf2, b_o, 1.0f, out, 256);
}

// round 16
// speedup vs baseline: 1.0710x; 1.0710x over previous
#include <cuda_runtime.h>
#include <cuda_fp16.h>
#include <cuda_bf16.h>
#include <cstdint>

#define B_  4
#define N_  4096
#define D_  256
#define HH  8
#define PP  9
#define DH  32
#define M_  (B_*N_)   // 16384
#define NOFF 144
#define NATT 72
#define NOA  216

// ---------------- device scratch (static) ----------------------------------
__device__ uint2  g_bfrag0[16 * 32 * 2 * 32];   // W_off|W_attn bf16 hi/lo (zero-padded)
__device__ uint2  g_bfrag1[16 * 32 * 2 * 32];   // W_v  fp16 (term0 = 64*W)
__device__ uint2  g_bfrag2[16 * 32 * 2 * 32];   // W_o  fp16 (term0 = 64*W)
__device__ float  g_boa[NOA];
__device__ float  g_offattn[(size_t)M_ * NOA];
__device__ __half g_vimg[(size_t)M_ * D_];      // [(b*8+h)][n=y*64+x][c]
__device__ __half g_headout[(size_t)M_ * D_];

// ---------------- helpers ----------------------------------------------------
__device__ __forceinline__ uint32_t bf2bits(float a, float b) {
    __nv_bfloat162 h = __floats2bfloat162_rn(a, b);
    return *reinterpret_cast<uint32_t*>(&h);
}
__device__ __forceinline__ uint32_t h2bits(float a, float b) {
    __half2 h = __floats2half2_rn(a, b);
    return *reinterpret_cast<uint32_t*>(&h);
}
__device__ __forceinline__ uint32_t smem_u32(const void* p) {
    uint32_t a;
    asm("{ .reg .u64 t; cvta.to.shared.u64 t, %1; cvt.u32.u64 %0, t; }"
        : "=r"(a) : "l"(p));
    return a;
}
__device__ __forceinline__ void mma_bf16(float* c,
        uint32_t a0, uint32_t a1, uint32_t a2, uint32_t a3,
        uint32_t b0, uint32_t b1) {
    asm("mma.sync.aligned.m16n8k16.row.col.f32.bf16.bf16.f32 "
        "{%0,%1,%2,%3}, {%4,%5,%6,%7}, {%8,%9}, {%0,%1,%2,%3};"
        : "+f"(c[0]), "+f"(c[1]), "+f"(c[2]), "+f"(c[3])
        : "r"(a0), "r"(a1), "r"(a2), "r"(a3), "r"(b0), "r"(b1));
}
__device__ __forceinline__ void mma_f16(float* c,
        uint32_t a0, uint32_t a1, uint32_t a2, uint32_t a3,
        uint32_t b0, uint32_t b1) {
    asm("mma.sync.aligned.m16n8k16.row.col.f32.f16.f16.f32 "
        "{%0,%1,%2,%3}, {%4,%5,%6,%7}, {%8,%9}, {%0,%1,%2,%3};"
        : "+f"(c[0]), "+f"(c[1]), "+f"(c[2]), "+f"(c[3])
        : "r"(a0), "r"(a1), "r"(a2), "r"(a3), "r"(b0), "r"(b1));
}
__device__ __forceinline__ void ldsm4(uint32_t addr,
        uint32_t& r0, uint32_t& r1, uint32_t& r2, uint32_t& r3) {
    asm volatile("ldmatrix.sync.aligned.m8n8.x4.shared.b16 {%0,%1,%2,%3}, [%4];"
                 : "=r"(r0), "=r"(r1), "=r"(r2), "=r"(r3) : "r"(addr));
}

// ---------------- pack: B -> fragment order -----------------------------------
__global__ void __launch_bounds__(256) pack_kernel(
        const float* __restrict__ Woff, const float* __restrict__ boff,
        const float* __restrict__ Watt, const float* __restrict__ batt,
        const float* __restrict__ Wv,   const float* __restrict__ Wo) {
    int idx = blockIdx.x * 256 + threadIdx.x;
    int mat = blockIdx.y;
    int lane = idx & 31;
    int term = (idx >> 5) & 1;
    int j    = (idx >> 6) & 31;
    int kk   = idx >> 11;
    int gid = lane >> 2, tig = lane & 3;
    int n = j * 8 + gid;
    int k0 = kk * 16 + tig * 2;

    float v[4];
#pragma unroll
    for (int q = 0; q < 4; q++) {
        int k = k0 + (q & 1) + (q >> 1) * 8;
        float w = 0.f;
        if (mat == 0) {
            if (n < NOFF)      w = Woff[k * NOFF + n];
            else if (n < NOA)  w = Watt[k * NATT + (n - NOFF)];
        } else if (mat == 1) {
            w = Wv[k * 256 + n];
        } else {
            w = Wo[k * 256 + n];
        }
        v[q] = w;
    }
    uint2 r;
    if (mat == 0) {
        if (term == 1) {
#pragma unroll
            for (int q = 0; q < 4; q++) {
                float hi = __bfloat162float(__float2bfloat16(v[q]));
                v[q] = v[q] - hi;
            }
        }
        r = make_uint2(bf2bits(v[0], v[1]), bf2bits(v[2], v[3]));
    } else {
#pragma unroll
        for (int q = 0; q < 4; q++) {
            float w64 = v[q] * 64.0f;
            if (term == 0) {
                v[q] = w64;
            } else {
                float hi = __half2float(__float2half_rn(w64));
                v[q] = w64 - hi;
            }
        }
        r = make_uint2(h2bits(v[0], v[1]), h2bits(v[2], v[3]));
    }
    if (mat == 0)      g_bfrag0[idx] = r;
    else if (mat == 1) g_bfrag1[idx] = r;
    else               g_bfrag2[idx] = r;

    if (mat == 0 && idx < NOA)
        g_boa[idx] = (idx < NOFF) ? boff[idx] : batt[idx - NOFF];
}

// ---------------- GEMM body (device): BM=128, BN=256, 512 threads ------------
// TERMS 3: A bf16 hi/lo, B bf16 hi/lo (3-term fp32 emu, offattn).
// TERMS 1: A fp16, B fp16 of 64*W, single MMA per step (vimg, W_o).
// AMODE 0: fp32 rows (lda); AMODE 1: sum of 3 temporal fp32 rows; AMODE 2: fp16 rows
// CMODE 0: fp32 row-major [ldc]; CMODE 1: fp16 vimg scatter
#define APITCH 528           // 256 elems * 2B + 16B pad
#define PLANE  (128 * APITCH)
template<int TERMS, int AMODE, int CMODE, int NCOUT>
__device__ __forceinline__ void gemm_body(
        char* smem, int blk,
        const void* __restrict__ Av, int lda,
        const uint2* __restrict__ Bfrag,
        const float* __restrict__ bias, float bscale,
        float* __restrict__ C, int ldc)
{
    char* HI = smem;
    const int tid = threadIdx.x;
    const int wid = tid >> 5, lane = tid & 31;
    const int warp_m = wid & 1, warp_n = wid >> 1;   // 2 x 8 warp grid
    const int mtile = blk * 128;
    const int nbase = warp_n * 32;
    const int gid = lane >> 2, tig = lane & 3;
    const bool active = (TERMS != 3) || (nbase < NOA);

    // ---- stage A tile: 128 rows x 256, 4 threads per row ----
    {
        const int row = tid >> 2;
        const int kcolq = (tid & 3) * 64;
        const int sw = (row & 7) << 5;
        char* hp = HI + row * APITCH;
        if (AMODE == 2) {
            const __half* Ap = (const __half*)Av + (size_t)(mtile + row) * lda + kcolq;
#pragma unroll
            for (int c = 0; c < 4; c++) {
                uint4 u0 = *(const uint4*)(Ap + c * 16);
                uint4 u1 = *(const uint4*)(Ap + c * 16 + 8);
                const int XS = ((tid & 3) * 128 + c * 32) ^ sw;
                *(uint4*)(hp + XS)      = u0;
                *(uint4*)(hp + XS + 16) = u1;
            }
        } else {
            const float* Ap = (const float*)Av + (size_t)(mtile + row) * lda + kcolq;
#pragma unroll
            for (int c = 0; c < 4; c++) {
                float v[16];
#pragma unroll
                for (int q = 0; q < 4; q++) {
                    float4 t0 = *(const float4*)(Ap + c * 16 + q * 4);
                    if (AMODE == 1) {
                        float4 t1 = *(const float4*)(Ap + c * 16 + q * 4 + 256);
                        float4 t2 = *(const float4*)(Ap + c * 16 + q * 4 + 512);
                        t0.x += t1.x + t2.x; t0.y += t1.y + t2.y;
                        t0.z += t1.z + t2.z; t0.w += t1.w + t2.w;
                    }
                    v[q * 4 + 0] = t0.x; v[q * 4 + 1] = t0.y;
                    v[q * 4 + 2] = t0.z; v[q * 4 + 3] = t0.w;
                }
                const int XS = ((tid & 3) * 128 + c * 32) ^ sw;
                if (TERMS == 1) {
                    uint32_t hp8[8];
#pragma unroll
                    for (int e = 0; e < 8; e++)
                        hp8[e] = h2bits(v[2 * e], v[2 * e + 1]);
                    *(uint4*)(hp + XS)      = make_uint4(hp8[0], hp8[1], hp8[2], hp8[3]);
                    *(uint4*)(hp + XS + 16) = make_uint4(hp8[4], hp8[5], hp8[6], hp8[7]);
                } else {
                    uint32_t hp8[8], lp8[8];
#pragma unroll
                    for (int e = 0; e < 8; e++) {
                        float v0 = v[2 * e], v1 = v[2 * e + 1];
                        float h0 = __bfloat162float(__float2bfloat16(v0));
                        float h1 = __bfloat162float(__float2bfloat16(v1));
                        hp8[e] = bf2bits(v0, v1);
                        lp8[e] = bf2bits(v0 - h0, v1 - h1);
                    }
                    *(uint4*)(hp + XS)              = make_uint4(hp8[0], hp8[1], hp8[2], hp8[3]);
                    *(uint4*)(hp + XS + 16)         = make_uint4(hp8[4], hp8[5], hp8[6], hp8[7]);
                    *(uint4*)(hp + PLANE + XS)      = make_uint4(lp8[0], lp8[1], lp8[2], lp8[3]);
                    *(uint4*)(hp + PLANE + XS + 16) = make_uint4(lp8[4], lp8[5], lp8[6], lp8[7]);
                }
            }
        }
    }

    // ---- B prefetch ----
    const int jg = warp_n * 4;
    const uint2* Bp = Bfrag + (size_t)jg * 64 + lane;
    uint2 bbuf[2][4][2];
    if (active) {
#pragma unroll
        for (int j = 0; j < 4; j++) {
            bbuf[0][j][0] = __ldg(Bp + j * 64);
            bbuf[1][j][0] = __ldg(Bp + 2048 + j * 64);
            if (TERMS == 3) {
                bbuf[0][j][1] = __ldg(Bp + j * 64 + 32);
                bbuf[1][j][1] = __ldg(Bp + 2048 + j * 64 + 32);
            }
        }
    }

    float acc[4][4][4];
#pragma unroll
    for (int mt = 0; mt < 4; mt++)
#pragma unroll
        for (int j = 0; j < 4; j++)
#pragma unroll
            for (int q = 0; q < 4; q++) acc[mt][j][q] = 0.f;

    __syncthreads();

    const int lrow = warp_m * 64 + (lane & 15);
    const uint32_t lanec = (lane >> 4) << 4;
    const uint32_t swr = (lrow & 7) << 5;
    const uint32_t hibase = smem_u32(HI + lrow * APITCH) + lanec;

    if (TERMS == 1) {
        uint32_t af[2][4];
        ldsm4(hibase + (0u ^ swr), af[0][0], af[0][1], af[0][2], af[0][3]);
        for (int kk = 0; kk < 16; kk++) {
            const int buf = kk & 1;
#pragma unroll
            for (int mt = 0; mt < 4; mt++) {
                const int cur = mt & 1;
                if (!(kk == 15 && mt == 3)) {
                    const int nmt = (mt + 1) & 3;
                    const int nkk = (mt == 3) ? kk + 1 : kk;
                    const uint32_t nkoff = ((uint32_t)(nkk * 32)) ^ swr;
                    ldsm4(hibase + nmt * (16 * APITCH) + nkoff,
                          af[cur ^ 1][0], af[cur ^ 1][1], af[cur ^ 1][2], af[cur ^ 1][3]);
                }
#pragma unroll
                for (int j = 0; j < 4; j++)
                    mma_f16(acc[mt][j], af[cur][0], af[cur][1], af[cur][2], af[cur][3],
                            bbuf[buf][j][0].x, bbuf[buf][j][0].y);
            }
            if (kk < 14) {
                const uint2* Bn = Bp + (size_t)(kk + 2) * 2048;
#pragma unroll
                for (int j = 0; j < 4; j++)
                    bbuf[buf][j][0] = __ldg(Bn + j * 64);
            }
        }
    } else if (active) {
        for (int kk = 0; kk < 16; kk++) {
            const uint32_t koff = ((uint32_t)(kk * 32)) ^ swr;
            const int buf = kk & 1;
#pragma unroll
            for (int mt = 0; mt < 4; mt++) {
                uint32_t ah0, ah1, ah2, ah3, al0, al1, al2, al3;
                uint32_t ad = hibase + mt * (16 * APITCH) + koff;
                ldsm4(ad, ah0, ah1, ah2, ah3);
                ldsm4(ad + PLANE, al0, al1, al2, al3);
#pragma unroll
                for (int j = 0; j < 4; j++)
                    mma_bf16(acc[mt][j], ah0, ah1, ah2, ah3,
                             bbuf[buf][j][0].x, bbuf[buf][j][0].y);
#pragma unroll
                for (int j = 0; j < 4; j++)
                    mma_bf16(acc[mt][j], al0, al1, al2, al3,
                             bbuf[buf][j][0].x, bbuf[buf][j][0].y);
#pragma unroll
                for (int j = 0; j < 4; j++)
                    mma_bf16(acc[mt][j], ah0, ah1, ah2, ah3,
                             bbuf[buf][j][1].x, bbuf[buf][j][1].y);
            }
            if (kk < 14) {
                const uint2* Bn = Bp + (size_t)(kk + 2) * 2048;
#pragma unroll
                for (int j = 0; j < 4; j++)
#pragma unroll
                    for (int t = 0; t < 2; t++)
                        bbuf[buf][j][t] = __ldg(Bn + j * 64 + t * 32);
            }
        }
    }

    // ---- epilogue ----
    const float cscale = (TERMS == 1) ? (1.0f / 64.0f) : 1.0f;
#pragma unroll
    for (int mt = 0; mt < 4; mt++) {
        int row0 = mtile + warp_m * 64 + mt * 16 + gid;
#pragma unroll
        for (int j = 0; j < 4; j++) {
            int col = nbase + j * 8 + tig * 2;
            if (col >= NCOUT) continue;
            float b0 = fmaf(bscale, bias[col],     acc[mt][j][0] * cscale);
            float b1 = fmaf(bscale, bias[col + 1], acc[mt][j][1] * cscale);
            float b2 = fmaf(bscale, bias[col],     acc[mt][j][2] * cscale);
            float b3 = fmaf(bscale, bias[col + 1], acc[mt][j][3] * cscale);
            if (CMODE == 0) {
                *(float2*)&C[(size_t)row0 * ldc + col] = make_float2(b0, b1);
                *(float2*)&C[(size_t)(row0 + 8) * ldc + col] = make_float2(b2, b3);
            } else {
                int h = col >> 5, cc = col & 31;
                int bb0 = row0 >> 12, nn0 = row0 & 4095;
                int gm1 = row0 + 8;
                int bb1 = gm1 >> 12, nn1 = gm1 & 4095;
                *(__half2*)&g_vimg[(((size_t)(bb0 * 8 + h) * 4096 + nn0) << 5) + cc] =
                    __floats2half2_rn(b0, b1);
                *(__half2*)&g_vimg[(((size_t)(bb1 * 8 + h) * 4096 + nn1) << 5) + cc] =
                    __floats2half2_rn(b2, b3);
            }
        }
    }
}

// ---------------- merged kernel: offattn (bids 0..127) + vimg (128..255) -----
__global__ void __launch_bounds__(512, 1) gemm_pair(
        const float* __restrict__ x,
        const uint2* __restrict__ bf_oa, const float* __restrict__ boa,
        float* __restrict__ offattn,
        const uint2* __restrict__ bf_v,  const float* __restrict__ bv)
{
    extern __shared__ char smem[];
    if (blockIdx.x < 128) {
        gemm_body<3, 0, 0, NOA>(smem, blockIdx.x, x + 256, 768,
                                bf_oa, boa, 1.0f, offattn, NOA);
    } else {
        gemm_body<1, 1, 1, 256>(smem, blockIdx.x - 128, x, 768,
                                bf_v, bv, 3.0f, nullptr, 0);
    }
}

// ---------------- W_o kernel ---------------------------------------------------
__global__ void __launch_bounds__(512, 1) gemm_wo(
        const __half* __restrict__ A,
        const uint2* __restrict__ Bfrag,
        const float* __restrict__ bias,
        float* __restrict__ C)
{
    extern __shared__ char smem[];
    gemm_body<1, 2, 0, 256>(smem, blockIdx.x, A, 256, Bfrag, bias, 1.0f, C, 256);
}

// ---------------- sampling: 4 bn per block, 4-channel lanes, fp16 out ---------
__global__ void __launch_bounds__(256) sample_kernel() {
    __shared__ int4   s_idx[4][HH * PP];
    __shared__ float4 s_wgt[4][HH * PP];

    const int bn0 = blockIdx.x * 4;
    const int t = threadIdx.x;

#pragma unroll
    for (int e = t; e < 4 * HH * PP; e += 256) {
        const int sub = e / (HH * PP);
        const int hp = e - sub * (HH * PP);
        const int h = hp / PP;
        const int p = hp - h * PP;
        const int bn = bn0 + sub;
        const int n = bn & 4095;
        const float* oa = g_offattn + (size_t)bn * NOA;

        float mx = -1e30f;
#pragma unroll
        for (int q = 0; q < PP; q++) mx = fmaxf(mx, oa[NOFF + h * PP + q]);
        float s = 0.f;
#pragma unroll
        for (int q = 0; q < PP; q++) s += __expf(oa[NOFF + h * PP + q] - mx);
        const float wa = __expf(oa[NOFF + h * PP + p] - mx) / s;

        const float ref_xn = (float)(n & 63) * (2.0f / 63.0f) - 1.0f;
        const float ref_yn = (float)(n >> 6) * (2.0f / 63.0f) - 1.0f;
        float ox = oa[h * 18 + p * 2 + 0];
        float oy = oa[h * 18 + p * 2 + 1];
        float gx = (ref_xn + ox + 1.0f) * 0.5f * 63.0f;
        float gy = (ref_yn + oy + 1.0f) * 0.5f * 63.0f;
        float x0f = floorf(gx), y0f = floorf(gy);
        int x0 = (int)x0f, y0 = (int)y0f;
        float wx1 = gx - x0f, wy1 = gy - y0f;
        float wx0 = 1.f - wx1, wy0 = 1.f - wy1;

        float vx0 = (x0 >= 0 && x0 < 64) ? 1.f : 0.f;
        float vx1 = (x0 >= -1 && x0 < 63) ? 1.f : 0.f;
        float vy0 = (y0 >= 0 && y0 < 64) ? 1.f : 0.f;
        float vy1 = (y0 >= -1 && y0 < 63) ? 1.f : 0.f;

        int cx0 = min(max(x0, 0), 63);
        int cx1 = min(max(x0 + 1, 0), 63);
        int cy0 = min(max(y0, 0), 63) * 64;
        int cy1 = min(max(y0 + 1, 0), 63) * 64;

        s_idx[sub][hp] = make_int4(cy0 + cx0, cy0 + cx1, cy1 + cx0, cy1 + cx1);
        s_wgt[sub][hp] = make_float4(wa * wx0 * wy0 * vx0 * vy0,
                                     wa * wx1 * wy0 * vx1 * vy0,
                                     wa * wx0 * wy1 * vx0 * vy1,
                                     wa * wx1 * wy1 * vx1 * vy1);
    }
    __syncthreads();

    const int sub = t >> 6;
    const int r = t & 63;
    const int h = r >> 3;
    const int c4 = r & 7;
    const int bn = bn0 + sub;
    const int b = bn >> 12;

    const uint2* img8 = (const uint2*)g_vimg
                      + (((size_t)(b * 8 + h) * 4096) << 3) + c4;

    float a0 = 0.f, a1 = 0.f, a2 = 0.f, a3 = 0.f;
#pragma unroll
    for (int p = 0; p < PP; p++) {
        int4   id = s_idx[sub][h * PP + p];
        float4 w  = s_wgt[sub][h * PP + p];
#pragma unroll
        for (int cr = 0; cr < 4; cr++) {
            int idx = (cr == 0) ? id.x : (cr == 1) ? id.y : (cr == 2) ? id.z : id.w;
            float ww = (cr == 0) ? w.x : (cr == 1) ? w.y : (cr == 2) ? w.z : w.w;
            uint2 v = __ldg(img8 + ((size_t)idx << 3));
            float2 f0 = __half22float2(*reinterpret_cast<__half2*>(&v.x));
            float2 f1 = __half22float2(*reinterpret_cast<__half2*>(&v.y));
            a0 = fmaf(ww, f0.x, a0);
            a1 = fmaf(ww, f0.y, a1);
            a2 = fmaf(ww, f1.x, a2);
            a3 = fmaf(ww, f1.y, a3);
        }
    }
    uint2 outv = make_uint2(h2bits(a0, a1), h2bits(a2, a3));
    *(uint2*)&g_headout[(size_t)bn * D_ + h * DH + c4 * 4] = outv;
}

// ---------------- launch --------------------------------------------------------
extern "C" void kernel_launch(void* const* d_in, const int* in_sizes, int n_in,
                              void* d_out, int out_size) {
    const float* x      = (const float*)d_in[0];
    const float* W_off  = (const float*)d_in[1];
    const float* b_off  = (const float*)d_in[2];
    const float* W_attn = (const float*)d_in[3];
    const float* b_attn = (const float*)d_in[4];
    const float* W_v    = (const float*)d_in[5];
    const float* b_v    = (const float*)d_in[6];
    const float* W_o    = (const float*)d_in[7];
    const float* b_o    = (const float*)d_in[8];
    float* out = (float*)d_out;

    uint2 *p_bf0, *p_bf1, *p_bf2;
    float *p_boa, *p_offattn;
    __half* p_headout;
    cudaGetSymbolAddress((void**)&p_bf0,     g_bfrag0);
    cudaGetSymbolAddress((void**)&p_bf1,     g_bfrag1);
    cudaGetSymbolAddress((void**)&p_bf2,     g_bfrag2);
    cudaGetSymbolAddress((void**)&p_boa,     g_boa);
    cudaGetSymbolAddress((void**)&p_offattn, g_offattn);
    cudaGetSymbolAddress((void**)&p_headout, g_headout);

    cudaFuncSetAttribute(gemm_pair,
                         cudaFuncAttributeMaxDynamicSharedMemorySize, 2 * PLANE);
    cudaFuncSetAttribute(gemm_wo,
                         cudaFuncAttributeMaxDynamicSharedMemorySize, PLANE);

    // 1. pack weights into fragment order
    pack_kernel<<<dim3(128, 3), 256>>>(W_off, b_off, W_attn, b_attn, W_v, W_o);

    // 2. merged: offattn (3-term bf16, bids 0..127) + vimg (1-term fp16, 128..255)
    gemm_pair<<<256, 512, 2 * PLANE>>>(x, p_bf0, p_boa, p_offattn, p_bf1, b_v);

    // 3. softmax + bilinear sampling + attention reduce -> fp16 headout
    sample_kernel<<<M_ / 4, 256>>>();

    // 4. output projection: headout(fp16) @ W_o + b_o (1-term fp16)
    gemm_wo<<<128, 512, PLANE>>>(p_headout, p_bf2, b_o, out);
}